// round 4
// baseline (speedup 1.0000x reference)
#include <cuda_runtime.h>
#include <cuda_bf16.h>

// EdgeAwareLoss: fused Sobel-edge-magnitude L1 loss, zero-smem register rolling.
// pred, target: [4,1,128,256,256] fp32 -> scalar mean(|mag_p - mag_t|).
// 512 slices of 256x256, zero-padded SAME 3x3 Sobel (cross-correlation).
//
// Separable: per row a[x] = v[x+1]-v[x-1], b[x] = v[x-1]+2v[x]+v[x+1];
// ex(y) = a(y-1)+2a(y)+a(y+1), ey(y) = b(y+1)-b(y-1).
//
// Thread owns 4 columns (float4). Warp-pair (h=0,1) covers a full 256-col row.
// Each pair rolls 32 rows; block = 8 warps = 4 pairs = 128 rows; 2 blocks/slice.

#define HW       256
#define NSLICES  512
#define NBLOCKS  1024                 // 2 x 512
#define N_TOTAL  33554432.0

__device__ double       g_accum = 0.0;
__device__ unsigned int g_count = 0u;

__device__ __forceinline__ void load_row(const float* __restrict__ img, int gy,
                                         int f4idx, bool needb, int bcol,
                                         float4& v, float& bval) {
    v = make_float4(0.f, 0.f, 0.f, 0.f);
    bval = 0.f;
    if ((unsigned)gy < (unsigned)HW) {           // warp-uniform branch
        const float* rp = img + (gy << 8);
        v = __ldg((const float4*)rp + f4idx);
        if (needb) bval = __ldg(rp + bcol);      // 1 active lane, L1 hit
    }
}

__device__ __forceinline__ void horiz4(const float4 v, const float bval,
                                       const int lane, const int h,
                                       float4& a, float4& b) {
    float lv = __shfl_up_sync(0xffffffffu, v.w, 1);
    float rv = __shfl_down_sync(0xffffffffu, v.x, 1);
    if (lane == 0)  lv = (h == 1) ? bval : 0.f;  // col-1 of image = pad
    if (lane == 31) rv = (h == 0) ? bval : 0.f;  // col 256 of image = pad
    a.x = v.y - lv;   a.y = v.z - v.x;  a.z = v.w - v.y;  a.w = rv - v.z;
    b.x = fmaf(2.f, v.x, lv + v.y);
    b.y = fmaf(2.f, v.y, v.x + v.z);
    b.z = fmaf(2.f, v.z, v.y + v.w);
    b.w = fmaf(2.f, v.w, v.z + rv);
}

__device__ __forceinline__ float px_term(float a1, float a2, float a3,
                                         float b1, float b3,
                                         float c1, float c2, float c3,
                                         float d1, float d3) {
    const float ex = fmaf(2.f, a2, a1 + a3);
    const float ey = b3 - b1;
    const float m2 = fmaf(ex, ex, fmaf(ey, ey, 1e-8f));
    const float mp = m2 * rsqrtf(m2);
    const float fx = fmaf(2.f, c2, c1 + c3);
    const float fy = d3 - d1;
    const float n2 = fmaf(fx, fx, fmaf(fy, fy, 1e-8f));
    const float mt = n2 * rsqrtf(n2);
    return fabsf(mp - mt);
}

__global__ __launch_bounds__(256, 2) void ea_kernel(
    const float* __restrict__ pred, const float* __restrict__ targ,
    float* __restrict__ out)
{
    const int tid  = threadIdx.x;
    const int lane = tid & 31;
    const int wid  = tid >> 5;          // 0..7
    const int h    = wid & 1;           // half-row: 0 = cols 0..127, 1 = 128..255
    const int pair = wid >> 1;          // 0..3
    const int r0   = blockIdx.x * 128 + pair * 32;
    const int f4idx = lane + (h << 5);
    const bool needb = h ? (lane == 0) : (lane == 31);
    const int  bcol  = h ? 127 : 128;

    const size_t base = (size_t)blockIdx.y << 16;   // slice * 65536
    const float* __restrict__ P = pred + base;
    const float* __restrict__ T = targ + base;

    float4 vP, vT, nP, nT;
    float  bvP, bvT, nbP, nbT;
    float4 a1P, a2P, b1P, b2P, a1T, a2T, b1T, b2T;

    // Prologue: rows r0-1 and r0.
    load_row(P, r0 - 1, f4idx, needb, bcol, vP, bvP);
    load_row(T, r0 - 1, f4idx, needb, bcol, vT, bvT);
    load_row(P, r0,     f4idx, needb, bcol, nP, nbP);
    load_row(T, r0,     f4idx, needb, bcol, nT, nbT);
    horiz4(vP, bvP, lane, h, a1P, b1P);
    horiz4(vT, bvT, lane, h, a1T, b1T);

    vP = nP; bvP = nbP; vT = nT; bvT = nbT;
    load_row(P, r0 + 1, f4idx, needb, bcol, nP, nbP);
    load_row(T, r0 + 1, f4idx, needb, bcol, nT, nbT);
    horiz4(vP, bvP, lane, h, a2P, b2P);
    horiz4(vT, bvT, lane, h, a2T, b2T);

    float4 acc = make_float4(0.f, 0.f, 0.f, 0.f);

    #pragma unroll 4
    for (int y = 0; y < 32; ++y) {
        // Consume prefetched row r0+1+y; prefetch row r0+2+y.
        vP = nP; bvP = nbP; vT = nT; bvT = nbT;
        if (y < 31) {
            load_row(P, r0 + 2 + y, f4idx, needb, bcol, nP, nbP);
            load_row(T, r0 + 2 + y, f4idx, needb, bcol, nT, nbT);
        }
        float4 a3P, b3P, a3T, b3T;
        horiz4(vP, bvP, lane, h, a3P, b3P);
        horiz4(vT, bvT, lane, h, a3T, b3T);

        acc.x += px_term(a1P.x, a2P.x, a3P.x, b1P.x, b3P.x,
                         a1T.x, a2T.x, a3T.x, b1T.x, b3T.x);
        acc.y += px_term(a1P.y, a2P.y, a3P.y, b1P.y, b3P.y,
                         a1T.y, a2T.y, a3T.y, b1T.y, b3T.y);
        acc.z += px_term(a1P.z, a2P.z, a3P.z, b1P.z, b3P.z,
                         a1T.z, a2T.z, a3T.z, b1T.z, b3T.z);
        acc.w += px_term(a1P.w, a2P.w, a3P.w, b1P.w, b3P.w,
                         a1T.w, a2T.w, a3T.w, b1T.w, b3T.w);

        a1P = a2P; a2P = a3P; b1P = b2P; b2P = b3P;
        a1T = a2T; a2T = a3T; b1T = b2T; b2T = b3T;
    }

    float sum = (acc.x + acc.y) + (acc.z + acc.w);

    #pragma unroll
    for (int o = 16; o > 0; o >>= 1)
        sum += __shfl_xor_sync(0xffffffffu, sum, o);

    __shared__ float wsum[8];
    if (lane == 0) wsum[wid] = sum;
    __syncthreads();

    if (tid == 0) {
        double s = 0.0;
        #pragma unroll
        for (int i = 0; i < 8; i++) s += (double)wsum[i];
        atomicAdd(&g_accum, s);
        __threadfence();
        const unsigned ticket = atomicAdd(&g_count, 1u);
        if (ticket == NBLOCKS - 1) {
            const double total = *((volatile double*)&g_accum);
            out[0] = (float)(total / N_TOTAL);
            g_accum = 0.0;                  // self-reset for graph replay
            g_count = 0u;
            __threadfence();
        }
    }
}

extern "C" void kernel_launch(void* const* d_in, const int* in_sizes, int n_in,
                              void* d_out, int out_size) {
    const float* pred = (const float*)d_in[0];
    const float* targ = (const float*)d_in[1];
    float* out = (float*)d_out;

    dim3 grid(2, NSLICES);   // 2 half-slices x 512 slices = 1024 blocks
    ea_kernel<<<grid, 256>>>(pred, targ, out);
}